// round 1
// baseline (speedup 1.0000x reference)
#include <cuda_runtime.h>

// ---------------- scratch (device globals; no allocation allowed) ----------------
__device__ float g_X [64*132*132*3];      //  13.4 MB  x in NHWC
__device__ float g_O1[64*65*65*200];      // 216.3 MB  layer1 out NHWC
__device__ float g_O2[64*31*31*400];      //  98.4 MB  layer2 out NHWC
__device__ float g_O3[64*15*15*800];      //  46.1 MB  layer3 out NHWC
__device__ float g_W1t[27*200];
__device__ float g_W2t[1800*400];
__device__ float g_W3t[3600*800];
__device__ float g_W4t[7200*10];

// ---------------- layout transforms ----------------
__global__ void k_nchw2nhwc(const float* __restrict__ in, float* __restrict__ out,
                            int B, int C, int H, int W) {
    int idx = blockIdx.x * blockDim.x + threadIdx.x;
    if (idx >= B * C * H * W) return;
    int c = idx % C;
    int t = idx / C;
    int x = t % W; t /= W;
    int y = t % H; t /= H;     // t = b now
    out[idx] = in[((t * C + c) * H + y) * W + x];
}

// W [oc][ic][ky][kx]  ->  Wt [k][oc],  k = (ky*3+kx)*IC + ic
__global__ void k_wt(const float* __restrict__ w, float* __restrict__ wt, int OC, int IC) {
    int idx = blockIdx.x * blockDim.x + threadIdx.x;
    if (idx >= OC * IC * 9) return;
    int oc  = idx % OC;
    int k   = idx / OC;
    int ic  = k % IC;
    int tap = k / IC;          // tap = ky*3+kx
    wt[idx] = w[(oc * IC + ic) * 9 + tap];
}

// ---------------- implicit GEMM with per-position gather ----------------
// C[n][m] = sum_k In[base(n) + off(k)] * Wt[k][m]
// n = b*P + p (P = OH*OW), base(n) = ((b*IH + ph)*IW + pw)*IC with ph = oy*stride + selh[p]
// epilogue: v = (mask[p] ? acc : 0) + bias[m]; optional relu; NHWC or NCHW store.
#define BN 64
#define BK 16
#define TN 4

template <int BMp, int TMp>
__global__ __launch_bounds__(256)
void k_gemm(const float* __restrict__ In, const float* __restrict__ Wt,
            const float* __restrict__ bias,
            const int* __restrict__ selh, const int* __restrict__ selw,
            const int* __restrict__ mask,
            float* __restrict__ Out,
            int IH, int IW, int IC, int OC,
            int OW, int P, int stride, int Ktot,
            int relu, int out_nchw)
{
    __shared__ float As[BK][BN + 1];
    __shared__ float Ws[BK][BMp];
    __shared__ int   s_base[BN];

    const int tid = threadIdx.x;
    const int n0  = blockIdx.x * BN;
    const int m0  = blockIdx.y * BMp;

    if (tid < BN) {
        int n  = n0 + tid;
        int b  = n / P;
        int p  = n - b * P;
        int oy = p / OW;
        int ox = p - oy * OW;
        int ph = oy * stride + (selh ? selh[p] : 0);
        int pw = ox * stride + (selw ? selw[p] : 0);
        s_base[tid] = ((b * IH + ph) * IW + pw) * IC;
    }
    __syncthreads();

    const int tx = tid & 15;   // N tile coord (16 x TN = 64)
    const int ty = tid >> 4;   // M tile coord (16 x TMp = BMp)

    constexpr int KSTEP = 256 / BMp;       // kk stride per load iter for W tile
    const int w_mm  = tid % BMp;
    const int w_kk0 = tid / BMp;
    const int a_kk  = tid & (BK - 1);
    const int a_nn0 = tid >> 4;            // 0..15; nn = a_nn0 + 16*r

    float acc[TMp][TN];
#pragma unroll
    for (int i = 0; i < TMp; i++)
#pragma unroll
        for (int j = 0; j < TN; j++) acc[i][j] = 0.f;

    for (int k0 = 0; k0 < Ktot; k0 += BK) {
        // ---- W tile: BK x BMp, coalesced over oc ----
#pragma unroll
        for (int r = 0; r < BK / KSTEP; r++) {
            int kk = w_kk0 + r * KSTEP;
            int k  = k0 + kk;
            int m  = m0 + w_mm;
            Ws[kk][w_mm] = (k < Ktot && m < OC) ? Wt[k * OC + m] : 0.f;
        }
        // ---- A tile: BK x BN via gather; each thread keeps one k (off hoisted) ----
        {
            int  k   = k0 + a_kk;
            bool ok  = (k < Ktot);
            int  off = 0;
            if (ok) {
                int c   = k % IC;
                int tap = k / IC;
                int ky  = tap / 3, kx = tap - ky * 3;
                off = (ky * IW + kx) * IC + c;
            }
#pragma unroll
            for (int r = 0; r < 4; r++) {
                int nn = a_nn0 + 16 * r;
                As[a_kk][nn] = ok ? In[s_base[nn] + off] : 0.f;
            }
        }
        __syncthreads();

#pragma unroll
        for (int kk = 0; kk < BK; kk++) {
            float ra[TN], rb[TMp];
#pragma unroll
            for (int j = 0; j < TN; j++)  ra[j] = As[kk][tx * TN + j];
#pragma unroll
            for (int i = 0; i < TMp; i++) rb[i] = Ws[kk][ty * TMp + i];
#pragma unroll
            for (int i = 0; i < TMp; i++)
#pragma unroll
                for (int j = 0; j < TN; j++)
                    acc[i][j] = fmaf(rb[i], ra[j], acc[i][j]);
        }
        __syncthreads();
    }

    // ---- epilogue: mask, bias, relu, store ----
#pragma unroll
    for (int j = 0; j < TN; j++) {
        int n = n0 + tx * TN + j;
        int b = n / P;
        int p = n - b * P;
        int mk = mask ? mask[p] : 1;
#pragma unroll
        for (int i = 0; i < TMp; i++) {
            int m = m0 + ty * TMp + i;
            if (m < OC) {
                float v = mk ? acc[i][j] : 0.f;
                v += __ldg(&bias[m]);
                if (relu) v = fmaxf(v, 0.f);
                if (out_nchw)
                    Out[(b * OC + m) * P + p] = v;   // [B][OC][P]
                else
                    Out[n * OC + m] = v;              // NHWC
            }
        }
    }
}

// ---------------- launch ----------------
extern "C" void kernel_launch(void* const* d_in, const int* in_sizes, int n_in,
                              void* d_out, int out_size) {
    const float* x     = (const float*)d_in[0];
    const float* w1    = (const float*)d_in[1];
    const float* b1    = (const float*)d_in[2];
    const float* w2    = (const float*)d_in[3];
    const float* b2    = (const float*)d_in[4];
    const float* w3    = (const float*)d_in[5];
    const float* b3    = (const float*)d_in[6];
    const float* w4    = (const float*)d_in[7];
    const float* b4    = (const float*)d_in[8];
    const int*   selh1 = (const int*)d_in[9];
    const int*   selw1 = (const int*)d_in[10];
    const int*   mask1 = (const int*)d_in[11];
    const int*   selh2 = (const int*)d_in[12];
    const int*   selw2 = (const int*)d_in[13];
    const int*   mask2 = (const int*)d_in[14];
    const int*   selh3 = (const int*)d_in[15];
    const int*   selw3 = (const int*)d_in[16];
    const int*   mask3 = (const int*)d_in[17];

    float *pX, *pO1, *pO2, *pO3, *pW1, *pW2, *pW3, *pW4;
    cudaGetSymbolAddress((void**)&pX,  g_X);
    cudaGetSymbolAddress((void**)&pO1, g_O1);
    cudaGetSymbolAddress((void**)&pO2, g_O2);
    cudaGetSymbolAddress((void**)&pO3, g_O3);
    cudaGetSymbolAddress((void**)&pW1, g_W1t);
    cudaGetSymbolAddress((void**)&pW2, g_W2t);
    cudaGetSymbolAddress((void**)&pW3, g_W3t);
    cudaGetSymbolAddress((void**)&pW4, g_W4t);

    // layout transforms
    {
        int tot = 64 * 3 * 132 * 132;
        k_nchw2nhwc<<<(tot + 255) / 256, 256>>>(x, pX, 64, 3, 132, 132);
    }
    k_wt<<<(200 * 27   + 255) / 256, 256>>>(w1, pW1, 200, 3);
    k_wt<<<(400 * 1800 + 255) / 256, 256>>>(w2, pW2, 400, 200);
    k_wt<<<(800 * 3600 + 255) / 256, 256>>>(w3, pW3, 800, 400);
    k_wt<<<(10  * 7200 + 255) / 256, 256>>>(w4, pW4, 10, 800);

    // layer 1: 132x132x3 -> 65x65x200, stride 2, K=27
    // N = 64*4225 = 270400 -> 4225 N-blocks; M = 200 -> 2 tiles of 128
    k_gemm<128, 8><<<dim3(4225, 2), 256>>>(pX, pW1, b1, selh1, selw1, mask1, pO1,
                                           132, 132, 3, 200, 65, 65 * 65, 2, 27, 1, 0);

    // layer 2: 65x65x200 -> 31x31x400, stride 2, K=1800
    // N = 64*961 = 61504 -> 961 blocks; M = 400 -> 4 tiles of 128
    k_gemm<128, 8><<<dim3(961, 4), 256>>>(pO1, pW2, b2, selh2, selw2, mask2, pO2,
                                          65, 65, 200, 400, 31, 31 * 31, 2, 1800, 1, 0);

    // layer 3: 31x31x400 -> 15x15x800 (ceil mode handled by sel data), stride 2, K=3600
    // N = 64*225 = 14400 -> 225 blocks; M = 800 -> 7 tiles of 128
    k_gemm<128, 8><<<dim3(225, 7), 256>>>(pO2, pW3, b3, selh3, selw3, mask3, pO3,
                                          31, 31, 400, 800, 15, 15 * 15, 2, 3600, 1, 0);

    // layer 4: dense 3x3 valid conv, stride 1, no mask/relu, NCHW output (flattened)
    // N = 64*169 = 10816 -> 169 blocks; M = 10 -> 1 tile of 64
    k_gemm<64, 4><<<dim3(169, 1), 256>>>(pO3, pW4, b4, nullptr, nullptr, nullptr,
                                         (float*)d_out,
                                         15, 15, 800, 10, 13, 13 * 13, 1, 7200, 0, 1);
}

// round 3
// speedup vs baseline: 2.5203x; 2.5203x over previous
#include <cuda_runtime.h>
#include <cuda_bf16.h>
#include <cstdint>

#define DINLINE __device__ __forceinline__

// ======================= scratch (device globals) =======================
__device__ __align__(16) float g_X [64*132*132*3];
__device__ __align__(16) float g_O1[64*65*65*200];
__device__ __align__(16) float g_O2[64*31*31*400];
__device__ __align__(16) float g_O3[64*15*15*800];
__device__ float g_W4t[7200*10];

// A: [Npad][2*PK]  (Ah | Al),  B: [OCpad][3*PK]  (Wh | Wl | Wh)
// L1: PK=64   Npad=270464 OCpad=256
// L2: PK=1856 Npad=61568  OCpad=512
// L3: PK=3648 Npad=14464  OCpad=896
__device__ __align__(16) __nv_bfloat16 g_A1[(size_t)270464*128];
__device__ __align__(16) __nv_bfloat16 g_A2[(size_t)61568*3712];
__device__ __align__(16) __nv_bfloat16 g_A3[(size_t)14464*7296];
__device__ __align__(16) __nv_bfloat16 g_B1[(size_t)256*192];
__device__ __align__(16) __nv_bfloat16 g_B2[(size_t)512*5568];
__device__ __align__(16) __nv_bfloat16 g_B3[(size_t)896*10944];

// ======================= helpers =======================
DINLINE uint32_t smem_u32(const void* p){
    uint32_t a;
    asm("{ .reg .u64 t; cvta.to.shared.u64 t, %1; cvt.u32.u64 %0, t; }" : "=r"(a) : "l"(p));
    return a;
}
DINLINE void cp16(uint32_t dst, const void* src){
    asm volatile("cp.async.cg.shared.global [%0], [%1], 16;" :: "r"(dst), "l"(src));
}
DINLINE void cp_commit(){ asm volatile("cp.async.commit_group;" ::: "memory"); }
DINLINE void cp_wait2(){ asm volatile("cp.async.wait_group 2;" ::: "memory"); }

DINLINE void ldmx4(uint32_t r[4], uint32_t addr){
    asm volatile("ldmatrix.sync.aligned.m8n8.x4.shared.b16 {%0,%1,%2,%3}, [%4];"
        : "=r"(r[0]), "=r"(r[1]), "=r"(r[2]), "=r"(r[3]) : "r"(addr));
}
DINLINE void mma_bf16(float c[4], const uint32_t a[4], uint32_t b0, uint32_t b1){
    asm volatile("mma.sync.aligned.m16n8k16.row.col.f32.bf16.bf16.f32 "
        "{%0,%1,%2,%3}, {%4,%5,%6,%7}, {%8,%9}, {%0,%1,%2,%3};"
        : "+f"(c[0]), "+f"(c[1]), "+f"(c[2]), "+f"(c[3])
        : "r"(a[0]), "r"(a[1]), "r"(a[2]), "r"(a[3]), "r"(b0), "r"(b1));
}

// ======================= layout transforms =======================
__global__ void k_nchw2nhwc(const float* __restrict__ in, float* __restrict__ out,
                            int B, int C, int H, int W) {
    int idx = blockIdx.x * blockDim.x + threadIdx.x;
    if (idx >= B * C * H * W) return;
    int c = idx % C;
    int t = idx / C;
    int x = t % W; t /= W;
    int y = t % H; t /= H;
    out[idx] = in[((t * C + c) * H + y) * W + x];
}

__global__ void k_wt(const float* __restrict__ w, float* __restrict__ wt, int OC, int IC) {
    int idx = blockIdx.x * blockDim.x + threadIdx.x;
    if (idx >= OC * IC * 9) return;
    int oc  = idx % OC;
    int k   = idx / OC;
    int ic  = k % IC;
    int tap = k / IC;
    wt[idx] = w[(oc * IC + ic) * 9 + tap];
}

// W[oc][ic][3][3] -> B[ocpad][3*PK] bf16 blocks (Wh | Wl | Wh), k = tap*IC + ic
__global__ void k_wsplit(const float* __restrict__ W, __nv_bfloat16* __restrict__ Bw,
                         int OC, int IC, int Klayer, int PK, int OCpad)
{
    long idx = (long)blockIdx.x*blockDim.x + threadIdx.x;
    long total = (long)OCpad * 3 * PK;
    if (idx >= total) return;
    int ldb = 3 * PK;
    int oc = (int)(idx / ldb);
    int k2 = (int)(idx - (long)oc*ldb);
    int blk = k2 / PK, kk = k2 - blk*PK;
    __nv_bfloat16 out = __float2bfloat16(0.f);
    if (oc < OC && kk < Klayer){
        int tap = kk/IC, c = kk - tap*IC;
        float x = W[((size_t)oc*IC + c)*9 + tap];
        __nv_bfloat16 h = __float2bfloat16(x);
        out = (blk == 1) ? __float2bfloat16(x - __bfloat162float(h)) : h;
    }
    Bw[idx] = out;
}

// layers 2/3 gather: A[n][2*PK] = (Ah | Al). IC % 8 == 0.
__global__ void k_gather(const float* __restrict__ In, __nv_bfloat16* __restrict__ A,
                         const int* __restrict__ selh, const int* __restrict__ selw,
                         int IH, int IW, int IC, int OW, int P, int stride,
                         int Klayer, int PK, int Nreal, int Npad)
{
    int vecs = PK >> 3;
    long idx = (long)blockIdx.x*blockDim.x + threadIdx.x;
    if (idx >= (long)Npad * vecs) return;
    int n = (int)(idx / vecs);
    int v = (int)(idx - (long)n*vecs);
    int kk = v << 3;
    __nv_bfloat16 h[8], l[8];
    if (n < Nreal && kk < Klayer){
        int b = n / P, p = n - b*P;
        int oy = p / OW, ox = p - oy*OW;
        int ph = oy*stride + selh[p], pw = ox*stride + selw[p];
        int tap = kk / IC, c = kk - tap*IC;
        int ky = tap/3, kx = tap - ky*3;
        const float* src = In + ((size_t)((b*IH+ph+ky)*IW) + (pw+kx))*IC + c;
        float x[8];
        *(float4*)&x[0] = *(const float4*)src;
        *(float4*)&x[4] = *(const float4*)(src+4);
#pragma unroll
        for (int i=0;i<8;i++){
            __nv_bfloat16 hh = __float2bfloat16(x[i]);
            h[i] = hh;
            l[i] = __float2bfloat16(x[i] - __bfloat162float(hh));
        }
    } else {
#pragma unroll
        for (int i=0;i<8;i++){ h[i]=__float2bfloat16(0.f); l[i]=h[i]; }
    }
    __nv_bfloat16* row = A + (size_t)n * (2*PK);
    *(uint4*)(row + kk)      = *(uint4*)h;
    *(uint4*)(row + PK + kk) = *(uint4*)l;
}

// layer 1: IC=3, K=27, PK=64; A row = 128 cols (Ah|Al)
__global__ void k_gather1(const float* __restrict__ X, __nv_bfloat16* __restrict__ A,
                          const int* __restrict__ selh, const int* __restrict__ selw)
{
    int n = blockIdx.x*blockDim.x + threadIdx.x;
    if (n >= 270464) return;
    __nv_bfloat16 row[128];
#pragma unroll
    for (int i=0;i<128;i++) row[i] = __float2bfloat16(0.f);
    if (n < 270400){
        int b = n / 4225, p = n - b*4225;
        int oy = p/65, ox = p - oy*65;
        int ph = oy*2 + selh[p], pw = ox*2 + selw[p];
        const float* base = X + ((size_t)(b*132+ph)*132 + pw)*3;
#pragma unroll
        for (int ky=0;ky<3;ky++){
#pragma unroll
            for (int t=0;t<9;t++){
                float x = base[ky*396 + t];
                int k = ky*9 + t;
                __nv_bfloat16 h = __float2bfloat16(x);
                row[k]      = h;
                row[64 + k] = __float2bfloat16(x - __bfloat162float(h));
            }
        }
    }
    uint4* dst = (uint4*)(A + (size_t)n*128);
    uint4* s = (uint4*)row;
#pragma unroll
    for (int i=0;i<16;i++) dst[i] = s[i];
}

// ======================= HMMA GEMM =======================
// CTA tile 128(n) x 128(oc), BK=64 bf16. 3-stage cp.async pipeline.
// smem per stage: A 16KB + B 16KB. Total 96KB dynamic.
// K-virtual = 3*PK, blocks (Ah*Wh, Ah*Wl, Al*Wh); A col base = blk==2 ? PK : 0.
static constexpr int STAGE = 32768;
static constexpr int SMEM_HM = 3 * STAGE;

DINLINE void stage_load(const __nv_bfloat16* __restrict__ Ag,
                        const __nv_bfloat16* __restrict__ Bg,
                        long ldA, long ldB, int Acol, int Bcol,
                        uint32_t sA, uint32_t sB, int tid)
{
#pragma unroll
    for (int i=0;i<4;i++){
        int q = tid + i*256;            // 1024 chunks: 128 rows x 8
        int row = q>>3, ch = q&7;
        cp16(sA + row*128 + ((ch ^ (row&7))<<4),
             Ag + (size_t)row*ldA + Acol + ch*8);
    }
#pragma unroll
    for (int i=0;i<4;i++){
        int q = tid + i*256;
        int row = q>>3, ch = q&7;
        cp16(sB + row*128 + ((ch ^ (row&7))<<4),
             Bg + (size_t)row*ldB + Bcol + ch*8);
    }
}

__global__ __launch_bounds__(256, 2)
void k_hmma(const __nv_bfloat16* __restrict__ A, const __nv_bfloat16* __restrict__ B,
            const float* __restrict__ bias, const int* __restrict__ mask,
            float* __restrict__ Out,
            int PK, int PKc, int OC, int P, int Nreal, int relu)
{
    extern __shared__ char smem[];
    const uint32_t sb = smem_u32(smem);
    const int tid = threadIdx.x, lane = tid & 31, warp = tid >> 5;
    const int wm = warp >> 1, wn = warp & 1;   // 4 x 2 warp grid; warp tile 32 x 64

    const long ldA = 2L*PK, ldB = 3L*PK;
    const __nv_bfloat16* Ag = A + (size_t)(blockIdx.y*128) * ldA;
    const __nv_bfloat16* Bg = B + (size_t)(blockIdx.x*128) * ldB;
    const int NC = 3 * PKc;

    float c[2][8][4];
#pragma unroll
    for (int i=0;i<2;i++)
#pragma unroll
        for (int j=0;j<8;j++)
#pragma unroll
            for (int k=0;k<4;k++) c[i][j][k] = 0.f;

    // prologue: stages 0,1
    {
        stage_load(Ag, Bg, ldA, ldB, 0, 0, sb, sb + 16384, tid);
        cp_commit();
        if (NC > 1){
            int blk = 1 / PKc, ci = 1 - blk*PKc;
            int ac = (blk==2 ? PK : 0) + ci*64;
            stage_load(Ag, Bg, ldA, ldB, ac, 64, sb + STAGE, sb + STAGE + 16384, tid);
        }
        cp_commit();
    }

#pragma unroll 1
    for (int cc = 0; cc < NC; cc++){
        if (cc + 2 < NC){
            int c2 = cc + 2;
            int blk = c2 / PKc, ci = c2 - blk*PKc;
            int ac = (blk==2 ? PK : 0) + ci*64;
            int s2 = c2 % 3;
            stage_load(Ag, Bg, ldA, ldB, ac, c2*64, sb + s2*STAGE, sb + s2*STAGE + 16384, tid);
        }
        cp_commit();
        cp_wait2();
        __syncthreads();

        const uint32_t sA = sb + (cc % 3)*STAGE;
        const uint32_t sB = sA + 16384;
        const int rA = wm*32 + (lane & 15);
        const int rB = wn*64 + (lane & 15);
#pragma unroll
        for (int ks = 0; ks < 4; ks++){
            const uint32_t choff = (uint32_t)(((ks*2 + (lane>>4)) ^ (lane&7)) << 4);
            uint32_t a[2][4], b[4][4];
#pragma unroll
            for (int mi = 0; mi < 2; mi++)
                ldmx4(a[mi], sA + (rA + mi*16)*128 + choff);
#pragma unroll
            for (int ni = 0; ni < 4; ni++)
                ldmx4(b[ni], sB + (rB + ni*16)*128 + choff);
#pragma unroll
            for (int mi = 0; mi < 2; mi++)
#pragma unroll
                for (int nj = 0; nj < 8; nj++)
                    mma_bf16(c[mi][nj], a[mi], b[nj>>1][nj&1], b[nj>>1][2+(nj&1)]);
        }
        __syncthreads();
    }

    // ---- epilogue: mask, bias, relu, store NHWC ----
    const int gm0 = blockIdx.y*128 + wm*32;
    const int oc0 = blockIdx.x*128 + wn*64;
#pragma unroll
    for (int mi = 0; mi < 2; mi++){
#pragma unroll
        for (int half = 0; half < 2; half++){
            int n = gm0 + mi*16 + half*8 + (lane >> 2);
            if (n >= Nreal) continue;
            int mk = 1;
            if (mask){ int p = n % P; mk = mask[p]; }
            float* orow = Out + (size_t)n * OC;
#pragma unroll
            for (int nj = 0; nj < 8; nj++){
                int oc = oc0 + nj*8 + (lane & 3)*2;
                float v0 = (mk ? c[mi][nj][half*2+0] : 0.f) + __ldg(&bias[oc < OC ? oc : 0]);
                float v1 = (mk ? c[mi][nj][half*2+1] : 0.f) + __ldg(&bias[(oc+1) < OC ? (oc+1) : 0]);
                if (relu){ v0 = fmaxf(v0, 0.f); v1 = fmaxf(v1, 0.f); }
                if (oc + 1 < OC){
                    float2 v = {v0, v1};
                    *(float2*)(orow + oc) = v;
                } else if (oc < OC){
                    orow[oc] = v0;
                }
            }
        }
    }
}

// ======================= SIMT GEMM (layer 4 only) =======================
#define BN 64
#define BK 16
#define TN 4
template <int BMp, int TMp>
__global__ __launch_bounds__(256)
void k_gemm(const float* __restrict__ In, const float* __restrict__ Wt,
            const float* __restrict__ bias,
            const int* __restrict__ mask,
            float* __restrict__ Out,
            int IH, int IW, int IC, int OC,
            int OW, int P, int stride, int Ktot,
            int relu, int out_nchw)
{
    __shared__ float As[BK][BN + 1];
    __shared__ float Ws[BK][BMp];
    __shared__ int   s_base[BN];

    const int tid = threadIdx.x;
    const int n0  = blockIdx.x * BN;
    const int m0  = blockIdx.y * BMp;

    if (tid < BN) {
        int n  = n0 + tid;
        int b  = n / P;
        int p  = n - b * P;
        int oy = p / OW;
        int ox = p - oy * OW;
        s_base[tid] = ((b * IH + oy*stride) * IW + ox*stride) * IC;
    }
    __syncthreads();

    const int tx = tid & 15;
    const int ty = tid >> 4;

    constexpr int KSTEP = 256 / BMp;
    const int w_mm  = tid % BMp;
    const int w_kk0 = tid / BMp;
    const int a_kk  = tid & (BK - 1);
    const int a_nn0 = tid >> 4;

    float acc[TMp][TN];
#pragma unroll
    for (int i = 0; i < TMp; i++)
#pragma unroll
        for (int j = 0; j < TN; j++) acc[i][j] = 0.f;

    for (int k0 = 0; k0 < Ktot; k0 += BK) {
#pragma unroll
        for (int r = 0; r < BK / KSTEP; r++) {
            int kk = w_kk0 + r * KSTEP;
            int k  = k0 + kk;
            int m  = m0 + w_mm;
            Ws[kk][w_mm] = (k < Ktot && m < OC) ? Wt[k * OC + m] : 0.f;
        }
        {
            int  k   = k0 + a_kk;
            bool ok  = (k < Ktot);
            int  off = 0;
            if (ok) {
                int c   = k % IC;
                int tap = k / IC;
                int ky  = tap / 3, kx = tap - ky * 3;
                off = (ky * IW + kx) * IC + c;
            }
#pragma unroll
            for (int r = 0; r < 4; r++) {
                int nn = a_nn0 + 16 * r;
                As[a_kk][nn] = ok ? In[s_base[nn] + off] : 0.f;
            }
        }
        __syncthreads();

#pragma unroll
        for (int kk = 0; kk < BK; kk++) {
            float ra[TN], rb[TMp];
#pragma unroll
            for (int j = 0; j < TN; j++)  ra[j] = As[kk][tx * TN + j];
#pragma unroll
            for (int i = 0; i < TMp; i++) rb[i] = Ws[kk][ty * TMp + i];
#pragma unroll
            for (int i = 0; i < TMp; i++)
#pragma unroll
                for (int j = 0; j < TN; j++)
                    acc[i][j] = fmaf(rb[i], ra[j], acc[i][j]);
        }
        __syncthreads();
    }

#pragma unroll
    for (int j = 0; j < TN; j++) {
        int n = n0 + tx * TN + j;
        int b = n / P;
        int p = n - b * P;
        int mk = mask ? mask[p] : 1;
#pragma unroll
        for (int i = 0; i < TMp; i++) {
            int m = m0 + ty * TMp + i;
            if (m < OC) {
                float v = mk ? acc[i][j] : 0.f;
                v += __ldg(&bias[m]);
                if (relu) v = fmaxf(v, 0.f);
                if (out_nchw)
                    Out[(b * OC + m) * P + p] = v;
                else
                    Out[n * OC + m] = v;
            }
        }
    }
}

// ======================= launch =======================
extern "C" void kernel_launch(void* const* d_in, const int* in_sizes, int n_in,
                              void* d_out, int out_size) {
    const float* x     = (const float*)d_in[0];
    const float* w1    = (const float*)d_in[1];
    const float* b1    = (const float*)d_in[2];
    const float* w2    = (const float*)d_in[3];
    const float* b2    = (const float*)d_in[4];
    const float* w3    = (const float*)d_in[5];
    const float* b3    = (const float*)d_in[6];
    const float* w4    = (const float*)d_in[7];
    const float* b4    = (const float*)d_in[8];
    const int*   selh1 = (const int*)d_in[9];
    const int*   selw1 = (const int*)d_in[10];
    const int*   mask1 = (const int*)d_in[11];
    const int*   selh2 = (const int*)d_in[12];
    const int*   selw2 = (const int*)d_in[13];
    const int*   mask2 = (const int*)d_in[14];
    const int*   selh3 = (const int*)d_in[15];
    const int*   selw3 = (const int*)d_in[16];
    const int*   mask3 = (const int*)d_in[17];

    float *pX, *pO1, *pO2, *pO3, *pW4;
    __nv_bfloat16 *pA1, *pA2, *pA3, *pB1, *pB2, *pB3;
    cudaGetSymbolAddress((void**)&pX,  g_X);
    cudaGetSymbolAddress((void**)&pO1, g_O1);
    cudaGetSymbolAddress((void**)&pO2, g_O2);
    cudaGetSymbolAddress((void**)&pO3, g_O3);
    cudaGetSymbolAddress((void**)&pW4, g_W4t);
    cudaGetSymbolAddress((void**)&pA1, g_A1);
    cudaGetSymbolAddress((void**)&pA2, g_A2);
    cudaGetSymbolAddress((void**)&pA3, g_A3);
    cudaGetSymbolAddress((void**)&pB1, g_B1);
    cudaGetSymbolAddress((void**)&pB2, g_B2);
    cudaGetSymbolAddress((void**)&pB3, g_B3);

    cudaFuncSetAttribute(k_hmma, cudaFuncAttributeMaxDynamicSharedMemorySize, SMEM_HM);

    // x -> NHWC
    {
        int tot = 64 * 3 * 132 * 132;
        k_nchw2nhwc<<<(tot + 255) / 256, 256>>>(x, pX, 64, 3, 132, 132);
    }

    // ---- layer 1: 132x132x3 -> 65x65x200, K=27, PK=64 ----
    k_gather1<<<(270464 + 255) / 256, 256>>>(pX, pA1, selh1, selw1);
    {
        long wt = (long)256 * 192;
        k_wsplit<<<(unsigned)((wt + 255) / 256), 256>>>(w1, pB1, 200, 3, 27, 64, 256);
    }
    k_hmma<<<dim3(2, 2113), 256, SMEM_HM>>>(pA1, pB1, b1, mask1, pO1,
                                            64, 1, 200, 4225, 270400, 1);

    // ---- layer 2: 65x65x200 -> 31x31x400, K=1800, PK=1856 ----
    {
        long tot = (long)61568 * (1856/8);
        k_gather<<<(unsigned)((tot + 255) / 256), 256>>>(pO1, pA2, selh2, selw2,
            65, 65, 200, 31, 961, 2, 1800, 1856, 61504, 61568);
        long wt = (long)512 * 5568;
        k_wsplit<<<(unsigned)((wt + 255) / 256), 256>>>(w2, pB2, 400, 200, 1800, 1856, 512);
        k_hmma<<<dim3(4, 481), 256, SMEM_HM>>>(pA2, pB2, b2, mask2, pO2,
                                               1856, 29, 400, 961, 61504, 1);
    }

    // ---- layer 3: 31x31x400 -> 15x15x800, K=3600, PK=3648 ----
    {
        long tot = (long)14464 * (3648/8);
        k_gather<<<(unsigned)((tot + 255) / 256), 256>>>(pO2, pA3, selh3, selw3,
            31, 31, 400, 15, 225, 2, 3600, 3648, 14400, 14464);
        long wt = (long)896 * 10944;
        k_wsplit<<<(unsigned)((wt + 255) / 256), 256>>>(w3, pB3, 800, 400, 3600, 3648, 896);
        k_hmma<<<dim3(7, 113), 256, SMEM_HM>>>(pA3, pB3, b3, mask3, pO3,
                                               3648, 57, 800, 225, 14400, 1);
    }

    // ---- layer 4: dense 3x3 conv, SIMT fp32, NCHW output ----
    k_wt<<<(10 * 7200 + 255) / 256, 256>>>(w4, pW4, 10, 800);
    k_gemm<64, 4><<<dim3(169, 1), 256>>>(pO3, pW4, b4, nullptr,
                                         (float*)d_out,
                                         15, 15, 800, 10, 13, 13 * 13, 1, 7200, 0, 1);
}